// round 13
// baseline (speedup 1.0000x reference)
#include <cuda_runtime.h>

// FFT convolution (S4): y[b,0,h,:] = first 4096 samples of linear conv(x[b,h,:], k[0,h,:])
// via length-8192 real FFT implemented as 4096-pt complex FFT with even/odd packing.
//
// R12: R11 (single-row, gmem-direct ends, stage-twiddle tables, packed f32x2) +
// __launch_bounds__(256,5) for 40 warps/SM (latency-bound kernel; occupancy is the
// binding resource) + Kf pairs packed into ulonglong2 (LDG.128: fewer loads, fewer
// address registers).

#define M 4096
#define H 1024
#define B 4
#define NT 256
#define NPAIR 1920           // pairs with kk !≡ 0 (mod 16), kk < 2048

#define PHI(a) ((a) ^ (((a) >> 4) & 15) ^ ((((a) >> 8) & 15) << 4))

typedef unsigned long long C;

__device__ float2 g_twm[M];              // e^{-2pi i e / M}
__device__ float2 g_twnT[NPAIR];         // e^{-pi i kk(t) / M}, t-ordered
__device__ float2 g_twS1[15 * 256];      // [(m-1)*256 + t] = e^{-2pi i m t / 4096}
__device__ float2 g_twS2[15 * 16];       // [(m-1)*16 + j]   = e^{-2pi i m j / 256}
__device__ ulonglong2 g_KfAB[H * NPAIR]; // {Kf[kk(t)], Kf[M-kk(t)]}
__device__ ulonglong2 g_KfCD[H * 128];   // u=0: {(Kf0.re,KfM.re), Kf[M/2]}; u>0: {Kf[16u], Kf[M-16u]}

// ---------------- packed complex: lo 32 bits = re, hi 32 bits = im ---------------------
__device__ __forceinline__ C packC(float re, float im) {
    C r; asm("mov.b64 %0, {%1, %2};" : "=l"(r) : "f"(re), "f"(im)); return r;
}
__device__ __forceinline__ void unpackC(C a, float& re, float& im) {
    asm("mov.b64 {%0, %1}, %2;" : "=f"(re), "=f"(im) : "l"(a));
}
__device__ __forceinline__ C padd(C a, C b) {
    C r; asm("add.rn.f32x2 %0, %1, %2;" : "=l"(r) : "l"(a), "l"(b)); return r;
}
__device__ __forceinline__ C pmul(C a, C b) {
    C r; asm("mul.rn.f32x2 %0, %1, %2;" : "=l"(r) : "l"(a), "l"(b)); return r;
}
__device__ __forceinline__ C pfma(C a, C b, C c) {
    C r; asm("fma.rn.f32x2 %0, %1, %2, %3;" : "=l"(r) : "l"(a), "l"(b), "l"(c)); return r;
}
__device__ __forceinline__ C psub(C a, C b) {           // a - b = fma(b, -1, a)
    return pfma(b, 0xBF800000BF800000ULL, a);
}
__device__ __forceinline__ C swapC(C a) {               // (im, re)
    unsigned lo, hi; asm("mov.b64 {%0, %1}, %2;" : "=r"(lo), "=r"(hi) : "l"(a));
    C r; asm("mov.b64 %0, {%1, %2};" : "=l"(r) : "r"(hi), "r"(lo)); return r;
}
__device__ __forceinline__ C conjC(C a)  { return a ^ 0x8000000000000000ULL; }
__device__ __forceinline__ C muli(C a)   { return swapC(a) ^ 0x80000000ULL; }
__device__ __forceinline__ C mulmi(C a)  { return swapC(a) ^ 0x8000000000000000ULL; }
__device__ __forceinline__ C splat_re(C a) {
    unsigned lo, hi; asm("mov.b64 {%0, %1}, %2;" : "=r"(lo), "=r"(hi) : "l"(a));
    C r; asm("mov.b64 %0, {%1, %2};" : "=l"(r) : "r"(lo), "r"(lo)); return r;
}
__device__ __forceinline__ C splat_im(C a) {
    unsigned lo, hi; asm("mov.b64 {%0, %1}, %2;" : "=r"(lo), "=r"(hi) : "l"(a));
    C r; asm("mov.b64 %0, {%1, %2};" : "=l"(r) : "r"(hi), "r"(hi)); return r;
}
__device__ __forceinline__ C cmul(C a, C b) {
    return pfma(splat_im(a), muli(b), pmul(splat_re(a), b));
}
__device__ __forceinline__ C cmulc(C a, C b) { return cmul(a, conjC(b)); }
__device__ __forceinline__ C cmulK(C a, float cr, float ci) {
    return pfma(splat_im(a), packC(-ci, cr), pmul(splat_re(a), packC(cr, ci)));
}

#define CC 0.70710678118654752f
#define HALFC 0x3F0000003F000000ULL     // (0.5, 0.5)
#define SCALEC 0x3980000039800000ULL    // (2^-12, 2^-12) = 1/M

// cos/sin(k*pi/8)
__device__ __forceinline__ constexpr float w16c(int k) {
    return (k == 0) ? 1.f : (k == 1) ? 0.9238795325112867f : (k == 2) ? 0.7071067811865476f
         : (k == 3) ? 0.3826834323650898f : (k == 4) ? 0.f : (k == 5) ? -0.3826834323650898f
         : (k == 6) ? -0.7071067811865476f : (k == 7) ? -0.9238795325112867f
         : (k == 8) ? -1.f : -0.9238795325112867f;
}
__device__ __forceinline__ constexpr float w16s(int k) {
    return (k == 0) ? 0.f : (k == 1) ? 0.3826834323650898f : (k == 2) ? 0.7071067811865476f
         : (k == 3) ? 0.9238795325112867f : (k == 4) ? 1.f : (k == 5) ? 0.9238795325112867f
         : (k == 6) ? 0.7071067811865476f : (k == 7) ? 0.3826834323650898f
         : (k == 8) ? 0.f : -0.3826834323650898f;
}

// pair enumeration (c1 fastest for conflict-free smem)
__device__ __forceinline__ void pair_digits(int t, int& c0, int& c1, int& c2) {
    c0 = 1 + (t >> 7);
    c1 = t & 15;
    c2 = (t >> 4) & 7;
}

__global__ void init_twiddles() {
    int i = blockIdx.x * blockDim.x + threadIdx.x;
    if (i < M) {
        float s, c;
        sincospif(-2.0f * (float)i / (float)M, &s, &c);
        g_twm[i] = make_float2(c, s);
    }
    int t = i - M;
    if (t >= 0 && t < NPAIR) {
        int c0, c1, c2; pair_digits(t, c0, c1, c2);
        int kk = 256 * c2 + 16 * c1 + c0;
        float s, c;
        sincospif(-(float)kk / (float)M, &s, &c);
        g_twnT[t] = make_float2(c, s);
    }
    int i2 = i - M - NPAIR;
    if (i2 >= 0 && i2 < 15 * 256) {
        int m = (i2 >> 8) + 1, tt = i2 & 255;
        float s, c;
        sincospif(-2.0f * (float)(m * tt) / 4096.0f, &s, &c);
        g_twS1[i2] = make_float2(c, s);
    }
    int i3 = i - M - NPAIR - 15 * 256;
    if (i3 >= 0 && i3 < 15 * 16) {
        int m = (i3 >> 4) + 1, j = i3 & 15;
        float s, c;
        sincospif(-2.0f * (float)(m * j) / 256.0f, &s, &c);
        g_twS2[i3] = make_float2(c, s);
    }
}

// ---------------- DFT building blocks --------------------------------------------------

template <bool FWD>
__device__ __forceinline__ void dft4(C& A, C& Bv, C& Cv, C& D) {
    C t0 = padd(A, Cv), t1 = psub(A, Cv), t2 = padd(Bv, D), t3 = psub(Bv, D);
    A = padd(t0, t2); Cv = psub(t0, t2);
    C j = FWD ? mulmi(t3) : muli(t3);
    Bv = padd(t1, j); D = psub(t1, j);
}

template <bool FWD, int E>
__device__ __forceinline__ C cw16(C a) {
    if (E == 4) return FWD ? mulmi(a) : muli(a);
    return cmulK(a, w16c(E), FWD ? -w16s(E) : w16s(E));
}

// natural input, output X[m] at slot perm(m) = ((m&3)<<2)|(m>>2)
template <bool FWD>
__device__ __forceinline__ void dft16(C* r) {
    dft4<FWD>(r[0], r[4], r[8], r[12]);
    dft4<FWD>(r[1], r[5], r[9], r[13]);
    dft4<FWD>(r[2], r[6], r[10], r[14]);
    dft4<FWD>(r[3], r[7], r[11], r[15]);
    r[5]  = cw16<FWD, 1>(r[5]);
    r[9]  = cw16<FWD, 2>(r[9]);
    r[13] = cw16<FWD, 3>(r[13]);
    r[6]  = cw16<FWD, 2>(r[6]);
    r[10] = cw16<FWD, 4>(r[10]);
    r[14] = cw16<FWD, 6>(r[14]);
    r[7]  = cw16<FWD, 3>(r[7]);
    r[11] = cw16<FWD, 6>(r[11]);
    r[15] = cw16<FWD, 9>(r[15]);
    dft4<FWD>(r[0],  r[1],  r[2],  r[3]);
    dft4<FWD>(r[4],  r[5],  r[6],  r[7]);
    dft4<FWD>(r[8],  r[9],  r[10], r[11]);
    dft4<FWD>(r[12], r[13], r[14], r[15]);
}
#define X16(r, m) (r)[(((m) & 3) << 2) | ((m) >> 2)]

__device__ __forceinline__ void dft8f(C* a) {
    C s0 = padd(a[0], a[4]), s1 = psub(a[0], a[4]), s2 = padd(a[2], a[6]), s3 = psub(a[2], a[6]);
    C E0 = padd(s0, s2), E2 = psub(s0, s2);
    C js = mulmi(s3);
    C E1 = padd(s1, js), E3 = psub(s1, js);
    C t0 = padd(a[1], a[5]), t1 = psub(a[1], a[5]), t2 = padd(a[3], a[7]), t3 = psub(a[3], a[7]);
    C O0 = padd(t0, t2), O2 = psub(t0, t2);
    C jt = mulmi(t3);
    C O1 = padd(t1, jt), O3 = psub(t1, jt);
    const C CC2 = packC(CC, CC);
    C P1 = pmul(CC2, padd(mulmi(O1), O1));
    C P2 = mulmi(O2);
    C P3 = pmul(CC2, psub(mulmi(O3), O3));
    a[0] = padd(E0, O0); a[4] = psub(E0, O0);
    a[1] = padd(E1, P1); a[5] = psub(E1, P1);
    a[2] = padd(E2, P2); a[6] = psub(E2, P2);
    a[3] = padd(E3, P3); a[7] = psub(E3, P3);
}

__device__ __forceinline__ void dft8i(C* a) {
    C s0 = padd(a[0], a[4]), s1 = psub(a[0], a[4]), s2 = padd(a[2], a[6]), s3 = psub(a[2], a[6]);
    C E0 = padd(s0, s2), E2 = psub(s0, s2);
    C js = muli(s3);
    C E1 = padd(s1, js), E3 = psub(s1, js);
    C t0 = padd(a[1], a[5]), t1 = psub(a[1], a[5]), t2 = padd(a[3], a[7]), t3 = psub(a[3], a[7]);
    C O0 = padd(t0, t2), O2 = psub(t0, t2);
    C jt = muli(t3);
    C O1 = padd(t1, jt), O3 = psub(t1, jt);
    const C CC2 = packC(CC, CC);
    C P1 = pmul(CC2, padd(muli(O1), O1));
    C P2 = muli(O2);
    C P3 = pmul(CC2, psub(muli(O3), O3));
    a[0] = padd(E0, O0); a[4] = psub(E0, O0);
    a[1] = padd(E1, P1); a[5] = psub(E1, P1);
    a[2] = padd(E2, P2); a[6] = psub(E2, P2);
    a[3] = padd(E3, P3); a[7] = psub(E3, P3);
}

#define TWM  ((const C*)g_twm)
#define TWNT ((const C*)g_twnT)
#define TWS1 ((const C*)g_twS1)
#define TWS2 ((const C*)g_twS2)

// ---------------- stages (NT=256, 1 butterfly per thread per stage) --------------------

// fwd L=4096 (q=256): loads x DIRECTLY from gmem (logical t+256k, k<8; upper half of
// the zero-padded input is pruned), stores to swizzled smem. Twiddles from g_twS1.
__device__ __forceinline__ void fwd_stage1(C* __restrict__ z, const C* __restrict__ src, int t) {
    const int d0 = t & 15, d1 = (t >> 4) & 15;
    const int Cb = (d0 ^ d1) | (d1 << 4);
    C a[8], b[8];
#pragma unroll
    for (int k = 0; k < 8; k++) a[k] = src[t + (k << 8)];
    b[0] = a[0];
#pragma unroll
    for (int k = 1; k < 8; k++) b[k] = cmulK(a[k], w16c(k), -w16s(k));
    dft8f(a);   // X[2r]
    dft8f(b);   // X[2r+1]
    z[Cb] = a[0];
#define ST1(m) z[Cb ^ (((m) << 4) ^ ((m) << 8))] = cmul(((m) & 1) ? b[(m) >> 1] : a[(m) >> 1], TWS1[((m) - 1) * 256 + t])
    ST1(1); ST1(2); ST1(3); ST1(4); ST1(5); ST1(6); ST1(7); ST1(8);
    ST1(9); ST1(10); ST1(11); ST1(12); ST1(13); ST1(14); ST1(15);
#undef ST1
}

// fwd L=256 (q=16); twiddles from g_twS2
__device__ __forceinline__ void fwd_stage2(C* __restrict__ z, int t) {
    const int bb = t >> 4, j = t & 15;
    const int Cb = j | (bb << 4) | (bb << 8);
    C r[16];
#pragma unroll
    for (int k = 0; k < 16; k++) r[k] = z[Cb ^ (17 * k)];
    dft16<true>(r);
    z[Cb] = r[0];
#define ST2(m) z[Cb ^ (17 * (m))] = cmul(X16(r, m), TWS2[((m) - 1) * 16 + j])
    ST2(1); ST2(2); ST2(3); ST2(4); ST2(5); ST2(6); ST2(7); ST2(8);
    ST2(9); ST2(10); ST2(11); ST2(12); ST2(13); ST2(14); ST2(15);
#undef ST2
}

// fwd L=16 (q=1, no twiddles)
__device__ __forceinline__ void fwd_stage3(C* __restrict__ z, int t) {
    const int bl = t & 15, bh = t >> 4;
    const int Cb = bl | (((bl ^ bh) & 15) << 4) | (bh << 8);
    C r[16];
#pragma unroll
    for (int k = 0; k < 16; k++) r[k] = z[Cb ^ k];
    dft16<true>(r);
#pragma unroll
    for (int m = 0; m < 16; m++) z[Cb ^ m] = X16(r, m);
}

// inv L=16 (no twiddles)
__device__ __forceinline__ void inv_stage1(C* __restrict__ z, int t) {
    const int bl = t & 15, bh = t >> 4;
    const int Cb = bl | (((bl ^ bh) & 15) << 4) | (bh << 8);
    C r[16];
#pragma unroll
    for (int k = 0; k < 16; k++) r[k] = z[Cb ^ k];
    dft16<false>(r);
#pragma unroll
    for (int m = 0; m < 16; m++) z[Cb ^ m] = X16(r, m);
}

// inv L=256 (conj twiddles on inputs, from g_twS2)
__device__ __forceinline__ void inv_stage2(C* __restrict__ z, int t) {
    const int bb = t >> 4, j = t & 15;
    const int Cb = j | (bb << 4) | (bb << 8);
    C r[16];
    r[0] = z[Cb];
#define LD2(k) r[k] = cmulc(z[Cb ^ (17 * (k))], TWS2[((k) - 1) * 16 + j])
    LD2(1); LD2(2); LD2(3); LD2(4); LD2(5); LD2(6); LD2(7); LD2(8);
    LD2(9); LD2(10); LD2(11); LD2(12); LD2(13); LD2(14); LD2(15);
#undef LD2
    dft16<false>(r);
#pragma unroll
    for (int m = 0; m < 16; m++) z[Cb ^ (17 * m)] = X16(r, m);
}

// inv L=4096 (conj twiddles from g_twS1; only outputs k<8 kept): stores y to gmem, scaled.
__device__ __forceinline__ void inv_stage3(const C* __restrict__ z, C* __restrict__ dst, int t) {
    const int d0 = t & 15, d1 = (t >> 4) & 15;
    const int Cb = (d0 ^ d1) | (d1 << 4);
    C ae[8], ao[8];
    ae[0] = z[Cb];
#define LD3(k) { C v = cmulc(z[Cb ^ (((k) << 4) ^ ((k) << 8))], TWS1[((k) - 1) * 256 + t]); \
                 if ((k) & 1) ao[(k) >> 1] = v; else ae[(k) >> 1] = v; }
    LD3(1); LD3(2); LD3(3); LD3(4); LD3(5); LD3(6); LD3(7); LD3(8);
    LD3(9); LD3(10); LD3(11); LD3(12); LD3(13); LD3(14); LD3(15);
#undef LD3
    dft8i(ae);
    dft8i(ao);
#pragma unroll
    for (int k = 0; k < 8; k++) {
        C v = padd(ae[k], cmulK(ao[k], w16c(k), w16s(k)));
        dst[t + (k << 8)] = pmul(v, SCALEC);
    }
}

// ---------------- pointwise helpers ----------------------------------------------------

__device__ __forceinline__ void pw(C& Zk, C& Zm, C tw, C K1, C K2) {
    C cm = conjC(Zm);
    C E = pmul(HALFC, padd(Zk, cm));
    C D = psub(Zk, cm);
    C O = pmul(HALFC, mulmi(D));
    C OT = cmul(O, tw);
    C X1  = padd(E, OT);
    C X2c = psub(E, OT);
    C Y1  = cmul(X1, K1);
    C Y2c = cmulc(X2c, K2);
    C Ey = pmul(HALFC, padd(Y1, Y2c));
    C G  = pmul(HALFC, psub(Y1, Y2c));
    C Oy = cmulc(G, tw);
    Zk = padd(Ey, muli(Oy));
    Zm = padd(conjC(Ey), swapC(Oy));
}

__device__ __forceinline__ void unpackX(C Zk, C Zm, C tw, C& X1, C& X2) {
    C cm = conjC(Zm);
    C E = pmul(HALFC, padd(Zk, cm));
    C D = psub(Zk, cm);
    C O = pmul(HALFC, mulmi(D));
    C OT = cmul(O, tw);
    X1 = padd(E, OT);
    X2 = conjC(psub(E, OT));
}

// ---------------- kernel spectra -------------------------------------------------------
__global__ __launch_bounds__(NT, 5) void kf_kernel(const float* __restrict__ kin) {
    __shared__ C z[M];
    const int h = blockIdx.x;
    const int tid = threadIdx.x;
    const C* krow2 = (const C*)(kin + (size_t)h * M);
    fwd_stage1(z, krow2, tid); __syncthreads();
    fwd_stage2(z, tid); __syncthreads();
    fwd_stage3(z, tid); __syncthreads();

    // boundary bins kk ≡ 0 (mod 16)
    if (tid < 128) {
        int u = tid;
        if (u == 0) {
            float zr, zi;
            unpackC(z[0], zr, zi);
            ulonglong2 v;
            v.x = packC(zr + zi, zr - zi);     // (Kf[0].re, Kf[M].re)
            v.y = conjC(z[8]);                 // Kf[M/2]
            g_KfCD[(size_t)h * 128] = v;
        } else {
            int p = 16 * (u & 15) + (u >> 4);
            int w = 256 - u;
            int q = 16 * (w & 15) + ((w >> 4) & 15);
            ulonglong2 v;
            unpackX(z[PHI(p)], z[PHI(q)], TWM[u << 3], v.x, v.y);  // Kf[16u], Kf[M-16u]
            g_KfCD[(size_t)h * 128 + u] = v;
        }
    }
    // main pairs
    for (int t = tid; t < NPAIR; t += NT) {
        int c0, c1, c2; pair_digits(t, c0, c1, c2);
        int p = 256 * c0 + 16 * c1 + c2;
        int q = 4351 - p;
        ulonglong2 v;
        unpackX(z[PHI(p)], z[PHI(q)], TWNT[t], v.x, v.y);          // Kf[kk], Kf[M-kk]
        g_KfAB[(size_t)h * NPAIR + t] = v;
    }
}

// ---------------- main conv (single row per CTA) ---------------------------------------
__global__ __launch_bounds__(NT, 5) void conv_kernel(const float* __restrict__ x,
                                                     float* __restrict__ y) {
    __shared__ C z[M];
    const int row = blockIdx.x;            // b*H + h
    const int h = row & (H - 1);
    const int tid = threadIdx.x;
    const C* xrow2 = (const C*)(x + (size_t)row * M);
    C* yrow2 = (C*)(y + (size_t)row * M);

    fwd_stage1(z, xrow2, tid); __syncthreads();
    fwd_stage2(z, tid); __syncthreads();
    fwd_stage3(z, tid); __syncthreads();

    const ulonglong2* __restrict__ KAB = g_KfAB + (size_t)h * NPAIR;
    const ulonglong2* __restrict__ KCD = g_KfCD + (size_t)h * 128;
    // boundary bins kk ≡ 0 (mod 16)
    if (tid < 128) {
        int u = tid;
        if (u == 0) {
            ulonglong2 Kv = KCD[0];
            float zr, zi, kc, kd;
            unpackC(z[0], zr, zi);
            unpackC(Kv.x, kc, kd);
            float Y0 = (zr + zi) * kc;
            float Ym = (zr - zi) * kd;
            z[0] = packC(0.5f * (Y0 + Ym), 0.5f * (Y0 - Ym));
            z[8] = cmulc(z[8], Kv.y);                              // bin M/2
        } else {
            int p = 16 * (u & 15) + (u >> 4);
            int w = 256 - u;
            int q = 16 * (w & 15) + ((w >> 4) & 15);
            int sp = PHI(p), sq = PHI(q);
            ulonglong2 Kv = KCD[u];
            C Zk = z[sp], Zm = z[sq];
            pw(Zk, Zm, TWM[u << 3], Kv.x, Kv.y);
            z[sp] = Zk;
            z[sq] = Zm;
        }
    }
    // main pairs
    for (int t = tid; t < NPAIR; t += NT) {
        int c0, c1, c2; pair_digits(t, c0, c1, c2);
        int p = 256 * c0 + 16 * c1 + c2;
        int q = 4351 - p;
        int sp = PHI(p), sq = PHI(q);
        ulonglong2 Kv = KAB[t];
        C Zk = z[sp], Zm = z[sq];
        pw(Zk, Zm, TWNT[t], Kv.x, Kv.y);
        z[sp] = Zk;
        z[sq] = Zm;
    }
    __syncthreads();
    inv_stage1(z, tid); __syncthreads();
    inv_stage2(z, tid); __syncthreads();
    inv_stage3(z, yrow2, tid);
}

extern "C" void kernel_launch(void* const* d_in, const int* in_sizes, int n_in,
                              void* d_out, int out_size) {
    const float* x;
    const float* k;
    if (in_sizes[0] == B * H * M) {           // x is the larger tensor
        x = (const float*)d_in[0];
        k = (const float*)d_in[1];
    } else {
        x = (const float*)d_in[1];
        k = (const float*)d_in[0];
    }
    float* y = (float*)d_out;

    const int ninit = M + NPAIR + 15 * 256 + 15 * 16;
    init_twiddles<<<(ninit + 511) / 512, 512>>>();
    kf_kernel<<<H, NT>>>(k);
    conv_kernel<<<B * H, NT>>>(x, y);
}

// round 14
// speedup vs baseline: 1.1296x; 1.1296x over previous
#include <cuda_runtime.h>

// FFT convolution (S4): y[b,0,h,:] = first 4096 samples of linear conv(x[b,h,:], k[0,h,:])
// via length-8192 real FFT implemented as 4096-pt complex FFT with even/odd packing.
//
// R13: R11 configuration (__launch_bounds__(256,4) — the proven occupancy sweet spot;
// R12's occ=5 regressed via spills) + R12's ulonglong2-packed Kf tables (LDG.128,
// fewer loads/address regs) with the gmem load hoisted ahead of the smem reads in
// the pointwise loop.

#define M 4096
#define H 1024
#define B 4
#define NT 256
#define NPAIR 1920           // pairs with kk !≡ 0 (mod 16), kk < 2048

#define PHI(a) ((a) ^ (((a) >> 4) & 15) ^ ((((a) >> 8) & 15) << 4))

typedef unsigned long long C;

__device__ float2 g_twm[M];              // e^{-2pi i e / M}
__device__ float2 g_twnT[NPAIR];         // e^{-pi i kk(t) / M}, t-ordered
__device__ float2 g_twS1[15 * 256];      // [(m-1)*256 + t] = e^{-2pi i m t / 4096}
__device__ float2 g_twS2[15 * 16];       // [(m-1)*16 + j]   = e^{-2pi i m j / 256}
__device__ ulonglong2 g_KfAB[H * NPAIR]; // {Kf[kk(t)], Kf[M-kk(t)]}
__device__ ulonglong2 g_KfCD[H * 128];   // u=0: {(Kf0.re,KfM.re), Kf[M/2]}; u>0: {Kf[16u], Kf[M-16u]}

// ---------------- packed complex: lo 32 bits = re, hi 32 bits = im ---------------------
__device__ __forceinline__ C packC(float re, float im) {
    C r; asm("mov.b64 %0, {%1, %2};" : "=l"(r) : "f"(re), "f"(im)); return r;
}
__device__ __forceinline__ void unpackC(C a, float& re, float& im) {
    asm("mov.b64 {%0, %1}, %2;" : "=f"(re), "=f"(im) : "l"(a));
}
__device__ __forceinline__ C padd(C a, C b) {
    C r; asm("add.rn.f32x2 %0, %1, %2;" : "=l"(r) : "l"(a), "l"(b)); return r;
}
__device__ __forceinline__ C pmul(C a, C b) {
    C r; asm("mul.rn.f32x2 %0, %1, %2;" : "=l"(r) : "l"(a), "l"(b)); return r;
}
__device__ __forceinline__ C pfma(C a, C b, C c) {
    C r; asm("fma.rn.f32x2 %0, %1, %2, %3;" : "=l"(r) : "l"(a), "l"(b), "l"(c)); return r;
}
__device__ __forceinline__ C psub(C a, C b) {           // a - b = fma(b, -1, a)
    return pfma(b, 0xBF800000BF800000ULL, a);
}
__device__ __forceinline__ C swapC(C a) {               // (im, re)
    unsigned lo, hi; asm("mov.b64 {%0, %1}, %2;" : "=r"(lo), "=r"(hi) : "l"(a));
    C r; asm("mov.b64 %0, {%1, %2};" : "=l"(r) : "r"(hi), "r"(lo)); return r;
}
__device__ __forceinline__ C conjC(C a)  { return a ^ 0x8000000000000000ULL; }
__device__ __forceinline__ C muli(C a)   { return swapC(a) ^ 0x80000000ULL; }
__device__ __forceinline__ C mulmi(C a)  { return swapC(a) ^ 0x8000000000000000ULL; }
__device__ __forceinline__ C splat_re(C a) {
    unsigned lo, hi; asm("mov.b64 {%0, %1}, %2;" : "=r"(lo), "=r"(hi) : "l"(a));
    C r; asm("mov.b64 %0, {%1, %2};" : "=l"(r) : "r"(lo), "r"(lo)); return r;
}
__device__ __forceinline__ C splat_im(C a) {
    unsigned lo, hi; asm("mov.b64 {%0, %1}, %2;" : "=r"(lo), "=r"(hi) : "l"(a));
    C r; asm("mov.b64 %0, {%1, %2};" : "=l"(r) : "r"(hi), "r"(hi)); return r;
}
__device__ __forceinline__ C cmul(C a, C b) {
    return pfma(splat_im(a), muli(b), pmul(splat_re(a), b));
}
__device__ __forceinline__ C cmulc(C a, C b) { return cmul(a, conjC(b)); }
__device__ __forceinline__ C cmulK(C a, float cr, float ci) {
    return pfma(splat_im(a), packC(-ci, cr), pmul(splat_re(a), packC(cr, ci)));
}

#define CC 0.70710678118654752f
#define HALFC 0x3F0000003F000000ULL     // (0.5, 0.5)
#define SCALEC 0x3980000039800000ULL    // (2^-12, 2^-12) = 1/M

// cos/sin(k*pi/8)
__device__ __forceinline__ constexpr float w16c(int k) {
    return (k == 0) ? 1.f : (k == 1) ? 0.9238795325112867f : (k == 2) ? 0.7071067811865476f
         : (k == 3) ? 0.3826834323650898f : (k == 4) ? 0.f : (k == 5) ? -0.3826834323650898f
         : (k == 6) ? -0.7071067811865476f : (k == 7) ? -0.9238795325112867f
         : (k == 8) ? -1.f : -0.9238795325112867f;
}
__device__ __forceinline__ constexpr float w16s(int k) {
    return (k == 0) ? 0.f : (k == 1) ? 0.3826834323650898f : (k == 2) ? 0.7071067811865476f
         : (k == 3) ? 0.9238795325112867f : (k == 4) ? 1.f : (k == 5) ? 0.9238795325112867f
         : (k == 6) ? 0.7071067811865476f : (k == 7) ? 0.3826834323650898f
         : (k == 8) ? 0.f : -0.3826834323650898f;
}

// pair enumeration (c1 fastest for conflict-free smem)
__device__ __forceinline__ void pair_digits(int t, int& c0, int& c1, int& c2) {
    c0 = 1 + (t >> 7);
    c1 = t & 15;
    c2 = (t >> 4) & 7;
}

__global__ void init_twiddles() {
    int i = blockIdx.x * blockDim.x + threadIdx.x;
    if (i < M) {
        float s, c;
        sincospif(-2.0f * (float)i / (float)M, &s, &c);
        g_twm[i] = make_float2(c, s);
    }
    int t = i - M;
    if (t >= 0 && t < NPAIR) {
        int c0, c1, c2; pair_digits(t, c0, c1, c2);
        int kk = 256 * c2 + 16 * c1 + c0;
        float s, c;
        sincospif(-(float)kk / (float)M, &s, &c);
        g_twnT[t] = make_float2(c, s);
    }
    int i2 = i - M - NPAIR;
    if (i2 >= 0 && i2 < 15 * 256) {
        int m = (i2 >> 8) + 1, tt = i2 & 255;
        float s, c;
        sincospif(-2.0f * (float)(m * tt) / 4096.0f, &s, &c);
        g_twS1[i2] = make_float2(c, s);
    }
    int i3 = i - M - NPAIR - 15 * 256;
    if (i3 >= 0 && i3 < 15 * 16) {
        int m = (i3 >> 4) + 1, j = i3 & 15;
        float s, c;
        sincospif(-2.0f * (float)(m * j) / 256.0f, &s, &c);
        g_twS2[i3] = make_float2(c, s);
    }
}

// ---------------- DFT building blocks --------------------------------------------------

template <bool FWD>
__device__ __forceinline__ void dft4(C& A, C& Bv, C& Cv, C& D) {
    C t0 = padd(A, Cv), t1 = psub(A, Cv), t2 = padd(Bv, D), t3 = psub(Bv, D);
    A = padd(t0, t2); Cv = psub(t0, t2);
    C j = FWD ? mulmi(t3) : muli(t3);
    Bv = padd(t1, j); D = psub(t1, j);
}

template <bool FWD, int E>
__device__ __forceinline__ C cw16(C a) {
    if (E == 4) return FWD ? mulmi(a) : muli(a);
    return cmulK(a, w16c(E), FWD ? -w16s(E) : w16s(E));
}

// natural input, output X[m] at slot perm(m) = ((m&3)<<2)|(m>>2)
template <bool FWD>
__device__ __forceinline__ void dft16(C* r) {
    dft4<FWD>(r[0], r[4], r[8], r[12]);
    dft4<FWD>(r[1], r[5], r[9], r[13]);
    dft4<FWD>(r[2], r[6], r[10], r[14]);
    dft4<FWD>(r[3], r[7], r[11], r[15]);
    r[5]  = cw16<FWD, 1>(r[5]);
    r[9]  = cw16<FWD, 2>(r[9]);
    r[13] = cw16<FWD, 3>(r[13]);
    r[6]  = cw16<FWD, 2>(r[6]);
    r[10] = cw16<FWD, 4>(r[10]);
    r[14] = cw16<FWD, 6>(r[14]);
    r[7]  = cw16<FWD, 3>(r[7]);
    r[11] = cw16<FWD, 6>(r[11]);
    r[15] = cw16<FWD, 9>(r[15]);
    dft4<FWD>(r[0],  r[1],  r[2],  r[3]);
    dft4<FWD>(r[4],  r[5],  r[6],  r[7]);
    dft4<FWD>(r[8],  r[9],  r[10], r[11]);
    dft4<FWD>(r[12], r[13], r[14], r[15]);
}
#define X16(r, m) (r)[(((m) & 3) << 2) | ((m) >> 2)]

__device__ __forceinline__ void dft8f(C* a) {
    C s0 = padd(a[0], a[4]), s1 = psub(a[0], a[4]), s2 = padd(a[2], a[6]), s3 = psub(a[2], a[6]);
    C E0 = padd(s0, s2), E2 = psub(s0, s2);
    C js = mulmi(s3);
    C E1 = padd(s1, js), E3 = psub(s1, js);
    C t0 = padd(a[1], a[5]), t1 = psub(a[1], a[5]), t2 = padd(a[3], a[7]), t3 = psub(a[3], a[7]);
    C O0 = padd(t0, t2), O2 = psub(t0, t2);
    C jt = mulmi(t3);
    C O1 = padd(t1, jt), O3 = psub(t1, jt);
    const C CC2 = packC(CC, CC);
    C P1 = pmul(CC2, padd(mulmi(O1), O1));
    C P2 = mulmi(O2);
    C P3 = pmul(CC2, psub(mulmi(O3), O3));
    a[0] = padd(E0, O0); a[4] = psub(E0, O0);
    a[1] = padd(E1, P1); a[5] = psub(E1, P1);
    a[2] = padd(E2, P2); a[6] = psub(E2, P2);
    a[3] = padd(E3, P3); a[7] = psub(E3, P3);
}

__device__ __forceinline__ void dft8i(C* a) {
    C s0 = padd(a[0], a[4]), s1 = psub(a[0], a[4]), s2 = padd(a[2], a[6]), s3 = psub(a[2], a[6]);
    C E0 = padd(s0, s2), E2 = psub(s0, s2);
    C js = muli(s3);
    C E1 = padd(s1, js), E3 = psub(s1, js);
    C t0 = padd(a[1], a[5]), t1 = psub(a[1], a[5]), t2 = padd(a[3], a[7]), t3 = psub(a[3], a[7]);
    C O0 = padd(t0, t2), O2 = psub(t0, t2);
    C jt = muli(t3);
    C O1 = padd(t1, jt), O3 = psub(t1, jt);
    const C CC2 = packC(CC, CC);
    C P1 = pmul(CC2, padd(muli(O1), O1));
    C P2 = muli(O2);
    C P3 = pmul(CC2, psub(muli(O3), O3));
    a[0] = padd(E0, O0); a[4] = psub(E0, O0);
    a[1] = padd(E1, P1); a[5] = psub(E1, P1);
    a[2] = padd(E2, P2); a[6] = psub(E2, P2);
    a[3] = padd(E3, P3); a[7] = psub(E3, P3);
}

#define TWM  ((const C*)g_twm)
#define TWNT ((const C*)g_twnT)
#define TWS1 ((const C*)g_twS1)
#define TWS2 ((const C*)g_twS2)

// ---------------- stages (NT=256, 1 butterfly per thread per stage) --------------------

// fwd L=4096 (q=256): loads x DIRECTLY from gmem (logical t+256k, k<8; upper half of
// the zero-padded input is pruned), stores to swizzled smem. Twiddles from g_twS1.
__device__ __forceinline__ void fwd_stage1(C* __restrict__ z, const C* __restrict__ src, int t) {
    const int d0 = t & 15, d1 = (t >> 4) & 15;
    const int Cb = (d0 ^ d1) | (d1 << 4);
    C a[8], b[8];
#pragma unroll
    for (int k = 0; k < 8; k++) a[k] = src[t + (k << 8)];
    b[0] = a[0];
#pragma unroll
    for (int k = 1; k < 8; k++) b[k] = cmulK(a[k], w16c(k), -w16s(k));
    dft8f(a);   // X[2r]
    dft8f(b);   // X[2r+1]
    z[Cb] = a[0];
#define ST1(m) z[Cb ^ (((m) << 4) ^ ((m) << 8))] = cmul(((m) & 1) ? b[(m) >> 1] : a[(m) >> 1], TWS1[((m) - 1) * 256 + t])
    ST1(1); ST1(2); ST1(3); ST1(4); ST1(5); ST1(6); ST1(7); ST1(8);
    ST1(9); ST1(10); ST1(11); ST1(12); ST1(13); ST1(14); ST1(15);
#undef ST1
}

// fwd L=256 (q=16); twiddles from g_twS2
__device__ __forceinline__ void fwd_stage2(C* __restrict__ z, int t) {
    const int bb = t >> 4, j = t & 15;
    const int Cb = j | (bb << 4) | (bb << 8);
    C r[16];
#pragma unroll
    for (int k = 0; k < 16; k++) r[k] = z[Cb ^ (17 * k)];
    dft16<true>(r);
    z[Cb] = r[0];
#define ST2(m) z[Cb ^ (17 * (m))] = cmul(X16(r, m), TWS2[((m) - 1) * 16 + j])
    ST2(1); ST2(2); ST2(3); ST2(4); ST2(5); ST2(6); ST2(7); ST2(8);
    ST2(9); ST2(10); ST2(11); ST2(12); ST2(13); ST2(14); ST2(15);
#undef ST2
}

// fwd L=16 (q=1, no twiddles)
__device__ __forceinline__ void fwd_stage3(C* __restrict__ z, int t) {
    const int bl = t & 15, bh = t >> 4;
    const int Cb = bl | (((bl ^ bh) & 15) << 4) | (bh << 8);
    C r[16];
#pragma unroll
    for (int k = 0; k < 16; k++) r[k] = z[Cb ^ k];
    dft16<true>(r);
#pragma unroll
    for (int m = 0; m < 16; m++) z[Cb ^ m] = X16(r, m);
}

// inv L=16 (no twiddles)
__device__ __forceinline__ void inv_stage1(C* __restrict__ z, int t) {
    const int bl = t & 15, bh = t >> 4;
    const int Cb = bl | (((bl ^ bh) & 15) << 4) | (bh << 8);
    C r[16];
#pragma unroll
    for (int k = 0; k < 16; k++) r[k] = z[Cb ^ k];
    dft16<false>(r);
#pragma unroll
    for (int m = 0; m < 16; m++) z[Cb ^ m] = X16(r, m);
}

// inv L=256 (conj twiddles on inputs, from g_twS2)
__device__ __forceinline__ void inv_stage2(C* __restrict__ z, int t) {
    const int bb = t >> 4, j = t & 15;
    const int Cb = j | (bb << 4) | (bb << 8);
    C r[16];
    r[0] = z[Cb];
#define LD2(k) r[k] = cmulc(z[Cb ^ (17 * (k))], TWS2[((k) - 1) * 16 + j])
    LD2(1); LD2(2); LD2(3); LD2(4); LD2(5); LD2(6); LD2(7); LD2(8);
    LD2(9); LD2(10); LD2(11); LD2(12); LD2(13); LD2(14); LD2(15);
#undef LD2
    dft16<false>(r);
#pragma unroll
    for (int m = 0; m < 16; m++) z[Cb ^ (17 * m)] = X16(r, m);
}

// inv L=4096 (conj twiddles from g_twS1; only outputs k<8 kept): stores y to gmem, scaled.
__device__ __forceinline__ void inv_stage3(const C* __restrict__ z, C* __restrict__ dst, int t) {
    const int d0 = t & 15, d1 = (t >> 4) & 15;
    const int Cb = (d0 ^ d1) | (d1 << 4);
    C ae[8], ao[8];
    ae[0] = z[Cb];
#define LD3(k) { C v = cmulc(z[Cb ^ (((k) << 4) ^ ((k) << 8))], TWS1[((k) - 1) * 256 + t]); \
                 if ((k) & 1) ao[(k) >> 1] = v; else ae[(k) >> 1] = v; }
    LD3(1); LD3(2); LD3(3); LD3(4); LD3(5); LD3(6); LD3(7); LD3(8);
    LD3(9); LD3(10); LD3(11); LD3(12); LD3(13); LD3(14); LD3(15);
#undef LD3
    dft8i(ae);
    dft8i(ao);
#pragma unroll
    for (int k = 0; k < 8; k++) {
        C v = padd(ae[k], cmulK(ao[k], w16c(k), w16s(k)));
        dst[t + (k << 8)] = pmul(v, SCALEC);
    }
}

// ---------------- pointwise helpers ----------------------------------------------------

__device__ __forceinline__ void pw(C& Zk, C& Zm, C tw, C K1, C K2) {
    C cm = conjC(Zm);
    C E = pmul(HALFC, padd(Zk, cm));
    C D = psub(Zk, cm);
    C O = pmul(HALFC, mulmi(D));
    C OT = cmul(O, tw);
    C X1  = padd(E, OT);
    C X2c = psub(E, OT);
    C Y1  = cmul(X1, K1);
    C Y2c = cmulc(X2c, K2);
    C Ey = pmul(HALFC, padd(Y1, Y2c));
    C G  = pmul(HALFC, psub(Y1, Y2c));
    C Oy = cmulc(G, tw);
    Zk = padd(Ey, muli(Oy));
    Zm = padd(conjC(Ey), swapC(Oy));
}

__device__ __forceinline__ void unpackX(C Zk, C Zm, C tw, C& X1, C& X2) {
    C cm = conjC(Zm);
    C E = pmul(HALFC, padd(Zk, cm));
    C D = psub(Zk, cm);
    C O = pmul(HALFC, mulmi(D));
    C OT = cmul(O, tw);
    X1 = padd(E, OT);
    X2 = conjC(psub(E, OT));
}

// ---------------- kernel spectra -------------------------------------------------------
__global__ __launch_bounds__(NT, 4) void kf_kernel(const float* __restrict__ kin) {
    __shared__ C z[M];
    const int h = blockIdx.x;
    const int tid = threadIdx.x;
    const C* krow2 = (const C*)(kin + (size_t)h * M);
    fwd_stage1(z, krow2, tid); __syncthreads();
    fwd_stage2(z, tid); __syncthreads();
    fwd_stage3(z, tid); __syncthreads();

    // boundary bins kk ≡ 0 (mod 16)
    if (tid < 128) {
        int u = tid;
        if (u == 0) {
            float zr, zi;
            unpackC(z[0], zr, zi);
            ulonglong2 v;
            v.x = packC(zr + zi, zr - zi);     // (Kf[0].re, Kf[M].re)
            v.y = conjC(z[8]);                 // Kf[M/2]
            g_KfCD[(size_t)h * 128] = v;
        } else {
            int p = 16 * (u & 15) + (u >> 4);
            int w = 256 - u;
            int q = 16 * (w & 15) + ((w >> 4) & 15);
            ulonglong2 v;
            unpackX(z[PHI(p)], z[PHI(q)], TWM[u << 3], v.x, v.y);  // Kf[16u], Kf[M-16u]
            g_KfCD[(size_t)h * 128 + u] = v;
        }
    }
    // main pairs
    for (int t = tid; t < NPAIR; t += NT) {
        int c0, c1, c2; pair_digits(t, c0, c1, c2);
        int p = 256 * c0 + 16 * c1 + c2;
        int q = 4351 - p;
        ulonglong2 v;
        unpackX(z[PHI(p)], z[PHI(q)], TWNT[t], v.x, v.y);          // Kf[kk], Kf[M-kk]
        g_KfAB[(size_t)h * NPAIR + t] = v;
    }
}

// ---------------- main conv (single row per CTA, 4 CTAs/SM) ----------------------------
__global__ __launch_bounds__(NT, 4) void conv_kernel(const float* __restrict__ x,
                                                     float* __restrict__ y) {
    __shared__ C z[M];
    const int row = blockIdx.x;            // b*H + h
    const int h = row & (H - 1);
    const int tid = threadIdx.x;
    const C* xrow2 = (const C*)(x + (size_t)row * M);
    C* yrow2 = (C*)(y + (size_t)row * M);

    fwd_stage1(z, xrow2, tid); __syncthreads();
    fwd_stage2(z, tid); __syncthreads();
    fwd_stage3(z, tid); __syncthreads();

    const ulonglong2* __restrict__ KAB = g_KfAB + (size_t)h * NPAIR;
    const ulonglong2* __restrict__ KCD = g_KfCD + (size_t)h * 128;
    // boundary bins kk ≡ 0 (mod 16)
    if (tid < 128) {
        int u = tid;
        if (u == 0) {
            ulonglong2 Kv = KCD[0];
            float zr, zi, kc, kd;
            unpackC(z[0], zr, zi);
            unpackC(Kv.x, kc, kd);
            float Y0 = (zr + zi) * kc;
            float Ym = (zr - zi) * kd;
            z[0] = packC(0.5f * (Y0 + Ym), 0.5f * (Y0 - Ym));
            z[8] = cmulc(z[8], Kv.y);                              // bin M/2
        } else {
            int p = 16 * (u & 15) + (u >> 4);
            int w = 256 - u;
            int q = 16 * (w & 15) + ((w >> 4) & 15);
            int sp = PHI(p), sq = PHI(q);
            ulonglong2 Kv = KCD[u];
            C Zk = z[sp], Zm = z[sq];
            pw(Zk, Zm, TWM[u << 3], Kv.x, Kv.y);
            z[sp] = Zk;
            z[sq] = Zm;
        }
    }
    // main pairs (gmem loads issued before smem reads for overlap)
    for (int t = tid; t < NPAIR; t += NT) {
        ulonglong2 Kv = KAB[t];
        C tw = TWNT[t];
        int c0, c1, c2; pair_digits(t, c0, c1, c2);
        int p = 256 * c0 + 16 * c1 + c2;
        int q = 4351 - p;
        int sp = PHI(p), sq = PHI(q);
        C Zk = z[sp], Zm = z[sq];
        pw(Zk, Zm, tw, Kv.x, Kv.y);
        z[sp] = Zk;
        z[sq] = Zm;
    }
    __syncthreads();
    inv_stage1(z, tid); __syncthreads();
    inv_stage2(z, tid); __syncthreads();
    inv_stage3(z, yrow2, tid);
}

extern "C" void kernel_launch(void* const* d_in, const int* in_sizes, int n_in,
                              void* d_out, int out_size) {
    const float* x;
    const float* k;
    if (in_sizes[0] == B * H * M) {           // x is the larger tensor
        x = (const float*)d_in[0];
        k = (const float*)d_in[1];
    } else {
        x = (const float*)d_in[1];
        k = (const float*)d_in[0];
    }
    float* y = (float*)d_out;

    const int ninit = M + NPAIR + 15 * 256 + 15 * 16;
    init_twiddles<<<(ninit + 511) / 512, 512>>>();
    kf_kernel<<<H, NT>>>(k);
    conv_kernel<<<B * H, NT>>>(x, y);
}

// round 15
// speedup vs baseline: 1.1642x; 1.0306x over previous
#include <cuda_runtime.h>

// FFT convolution (S4): y[b,0,h,:] = first 4096 samples of linear conv(x[b,h,:], k[0,h,:])
// via length-8192 real FFT implemented as 4096-pt complex FFT with even/odd packing.
//
// R14: R13 + h-adjacent CTA scheduling (blockIdx -> (h = g>>2, b = g&3)) so the 4 rows
// sharing Kf[h] run in the same wave: Kf reads become L2 hits (DRAM Kf traffic /4).
// Pointwise loop unrolled 7+1 for LDG pipelining.

#define M 4096
#define H 1024
#define B 4
#define NT 256
#define NPAIR 1920           // pairs with kk !≡ 0 (mod 16), kk < 2048

#define PHI(a) ((a) ^ (((a) >> 4) & 15) ^ ((((a) >> 8) & 15) << 4))

typedef unsigned long long C;

__device__ float2 g_twm[M];              // e^{-2pi i e / M}
__device__ float2 g_twnT[NPAIR];         // e^{-pi i kk(t) / M}, t-ordered
__device__ float2 g_twS1[15 * 256];      // [(m-1)*256 + t] = e^{-2pi i m t / 4096}
__device__ float2 g_twS2[15 * 16];       // [(m-1)*16 + j]   = e^{-2pi i m j / 256}
__device__ ulonglong2 g_KfAB[H * NPAIR]; // {Kf[kk(t)], Kf[M-kk(t)]}
__device__ ulonglong2 g_KfCD[H * 128];   // u=0: {(Kf0.re,KfM.re), Kf[M/2]}; u>0: {Kf[16u], Kf[M-16u]}

// ---------------- packed complex: lo 32 bits = re, hi 32 bits = im ---------------------
__device__ __forceinline__ C packC(float re, float im) {
    C r; asm("mov.b64 %0, {%1, %2};" : "=l"(r) : "f"(re), "f"(im)); return r;
}
__device__ __forceinline__ void unpackC(C a, float& re, float& im) {
    asm("mov.b64 {%0, %1}, %2;" : "=f"(re), "=f"(im) : "l"(a));
}
__device__ __forceinline__ C padd(C a, C b) {
    C r; asm("add.rn.f32x2 %0, %1, %2;" : "=l"(r) : "l"(a), "l"(b)); return r;
}
__device__ __forceinline__ C pmul(C a, C b) {
    C r; asm("mul.rn.f32x2 %0, %1, %2;" : "=l"(r) : "l"(a), "l"(b)); return r;
}
__device__ __forceinline__ C pfma(C a, C b, C c) {
    C r; asm("fma.rn.f32x2 %0, %1, %2, %3;" : "=l"(r) : "l"(a), "l"(b), "l"(c)); return r;
}
__device__ __forceinline__ C psub(C a, C b) {           // a - b = fma(b, -1, a)
    return pfma(b, 0xBF800000BF800000ULL, a);
}
__device__ __forceinline__ C swapC(C a) {               // (im, re)
    unsigned lo, hi; asm("mov.b64 {%0, %1}, %2;" : "=r"(lo), "=r"(hi) : "l"(a));
    C r; asm("mov.b64 %0, {%1, %2};" : "=l"(r) : "r"(hi), "r"(lo)); return r;
}
__device__ __forceinline__ C conjC(C a)  { return a ^ 0x8000000000000000ULL; }
__device__ __forceinline__ C muli(C a)   { return swapC(a) ^ 0x80000000ULL; }
__device__ __forceinline__ C mulmi(C a)  { return swapC(a) ^ 0x8000000000000000ULL; }
__device__ __forceinline__ C splat_re(C a) {
    unsigned lo, hi; asm("mov.b64 {%0, %1}, %2;" : "=r"(lo), "=r"(hi) : "l"(a));
    C r; asm("mov.b64 %0, {%1, %2};" : "=l"(r) : "r"(lo), "r"(lo)); return r;
}
__device__ __forceinline__ C splat_im(C a) {
    unsigned lo, hi; asm("mov.b64 {%0, %1}, %2;" : "=r"(lo), "=r"(hi) : "l"(a));
    C r; asm("mov.b64 %0, {%1, %2};" : "=l"(r) : "r"(hi), "r"(hi)); return r;
}
__device__ __forceinline__ C cmul(C a, C b) {
    return pfma(splat_im(a), muli(b), pmul(splat_re(a), b));
}
__device__ __forceinline__ C cmulc(C a, C b) { return cmul(a, conjC(b)); }
__device__ __forceinline__ C cmulK(C a, float cr, float ci) {
    return pfma(splat_im(a), packC(-ci, cr), pmul(splat_re(a), packC(cr, ci)));
}

#define CC 0.70710678118654752f
#define HALFC 0x3F0000003F000000ULL     // (0.5, 0.5)
#define SCALEC 0x3980000039800000ULL    // (2^-12, 2^-12) = 1/M

// cos/sin(k*pi/8)
__device__ __forceinline__ constexpr float w16c(int k) {
    return (k == 0) ? 1.f : (k == 1) ? 0.9238795325112867f : (k == 2) ? 0.7071067811865476f
         : (k == 3) ? 0.3826834323650898f : (k == 4) ? 0.f : (k == 5) ? -0.3826834323650898f
         : (k == 6) ? -0.7071067811865476f : (k == 7) ? -0.9238795325112867f
         : (k == 8) ? -1.f : -0.9238795325112867f;
}
__device__ __forceinline__ constexpr float w16s(int k) {
    return (k == 0) ? 0.f : (k == 1) ? 0.3826834323650898f : (k == 2) ? 0.7071067811865476f
         : (k == 3) ? 0.9238795325112867f : (k == 4) ? 1.f : (k == 5) ? 0.9238795325112867f
         : (k == 6) ? 0.7071067811865476f : (k == 7) ? 0.3826834323650898f
         : (k == 8) ? 0.f : -0.3826834323650898f;
}

// pair enumeration (c1 fastest for conflict-free smem)
__device__ __forceinline__ void pair_digits(int t, int& c0, int& c1, int& c2) {
    c0 = 1 + (t >> 7);
    c1 = t & 15;
    c2 = (t >> 4) & 7;
}

__global__ void init_twiddles() {
    int i = blockIdx.x * blockDim.x + threadIdx.x;
    if (i < M) {
        float s, c;
        sincospif(-2.0f * (float)i / (float)M, &s, &c);
        g_twm[i] = make_float2(c, s);
    }
    int t = i - M;
    if (t >= 0 && t < NPAIR) {
        int c0, c1, c2; pair_digits(t, c0, c1, c2);
        int kk = 256 * c2 + 16 * c1 + c0;
        float s, c;
        sincospif(-(float)kk / (float)M, &s, &c);
        g_twnT[t] = make_float2(c, s);
    }
    int i2 = i - M - NPAIR;
    if (i2 >= 0 && i2 < 15 * 256) {
        int m = (i2 >> 8) + 1, tt = i2 & 255;
        float s, c;
        sincospif(-2.0f * (float)(m * tt) / 4096.0f, &s, &c);
        g_twS1[i2] = make_float2(c, s);
    }
    int i3 = i - M - NPAIR - 15 * 256;
    if (i3 >= 0 && i3 < 15 * 16) {
        int m = (i3 >> 4) + 1, j = i3 & 15;
        float s, c;
        sincospif(-2.0f * (float)(m * j) / 256.0f, &s, &c);
        g_twS2[i3] = make_float2(c, s);
    }
}

// ---------------- DFT building blocks --------------------------------------------------

template <bool FWD>
__device__ __forceinline__ void dft4(C& A, C& Bv, C& Cv, C& D) {
    C t0 = padd(A, Cv), t1 = psub(A, Cv), t2 = padd(Bv, D), t3 = psub(Bv, D);
    A = padd(t0, t2); Cv = psub(t0, t2);
    C j = FWD ? mulmi(t3) : muli(t3);
    Bv = padd(t1, j); D = psub(t1, j);
}

template <bool FWD, int E>
__device__ __forceinline__ C cw16(C a) {
    if (E == 4) return FWD ? mulmi(a) : muli(a);
    return cmulK(a, w16c(E), FWD ? -w16s(E) : w16s(E));
}

// natural input, output X[m] at slot perm(m) = ((m&3)<<2)|(m>>2)
template <bool FWD>
__device__ __forceinline__ void dft16(C* r) {
    dft4<FWD>(r[0], r[4], r[8], r[12]);
    dft4<FWD>(r[1], r[5], r[9], r[13]);
    dft4<FWD>(r[2], r[6], r[10], r[14]);
    dft4<FWD>(r[3], r[7], r[11], r[15]);
    r[5]  = cw16<FWD, 1>(r[5]);
    r[9]  = cw16<FWD, 2>(r[9]);
    r[13] = cw16<FWD, 3>(r[13]);
    r[6]  = cw16<FWD, 2>(r[6]);
    r[10] = cw16<FWD, 4>(r[10]);
    r[14] = cw16<FWD, 6>(r[14]);
    r[7]  = cw16<FWD, 3>(r[7]);
    r[11] = cw16<FWD, 6>(r[11]);
    r[15] = cw16<FWD, 9>(r[15]);
    dft4<FWD>(r[0],  r[1],  r[2],  r[3]);
    dft4<FWD>(r[4],  r[5],  r[6],  r[7]);
    dft4<FWD>(r[8],  r[9],  r[10], r[11]);
    dft4<FWD>(r[12], r[13], r[14], r[15]);
}
#define X16(r, m) (r)[(((m) & 3) << 2) | ((m) >> 2)]

__device__ __forceinline__ void dft8f(C* a) {
    C s0 = padd(a[0], a[4]), s1 = psub(a[0], a[4]), s2 = padd(a[2], a[6]), s3 = psub(a[2], a[6]);
    C E0 = padd(s0, s2), E2 = psub(s0, s2);
    C js = mulmi(s3);
    C E1 = padd(s1, js), E3 = psub(s1, js);
    C t0 = padd(a[1], a[5]), t1 = psub(a[1], a[5]), t2 = padd(a[3], a[7]), t3 = psub(a[3], a[7]);
    C O0 = padd(t0, t2), O2 = psub(t0, t2);
    C jt = mulmi(t3);
    C O1 = padd(t1, jt), O3 = psub(t1, jt);
    const C CC2 = packC(CC, CC);
    C P1 = pmul(CC2, padd(mulmi(O1), O1));
    C P2 = mulmi(O2);
    C P3 = pmul(CC2, psub(mulmi(O3), O3));
    a[0] = padd(E0, O0); a[4] = psub(E0, O0);
    a[1] = padd(E1, P1); a[5] = psub(E1, P1);
    a[2] = padd(E2, P2); a[6] = psub(E2, P2);
    a[3] = padd(E3, P3); a[7] = psub(E3, P3);
}

__device__ __forceinline__ void dft8i(C* a) {
    C s0 = padd(a[0], a[4]), s1 = psub(a[0], a[4]), s2 = padd(a[2], a[6]), s3 = psub(a[2], a[6]);
    C E0 = padd(s0, s2), E2 = psub(s0, s2);
    C js = muli(s3);
    C E1 = padd(s1, js), E3 = psub(s1, js);
    C t0 = padd(a[1], a[5]), t1 = psub(a[1], a[5]), t2 = padd(a[3], a[7]), t3 = psub(a[3], a[7]);
    C O0 = padd(t0, t2), O2 = psub(t0, t2);
    C jt = muli(t3);
    C O1 = padd(t1, jt), O3 = psub(t1, jt);
    const C CC2 = packC(CC, CC);
    C P1 = pmul(CC2, padd(muli(O1), O1));
    C P2 = muli(O2);
    C P3 = pmul(CC2, psub(muli(O3), O3));
    a[0] = padd(E0, O0); a[4] = psub(E0, O0);
    a[1] = padd(E1, P1); a[5] = psub(E1, P1);
    a[2] = padd(E2, P2); a[6] = psub(E2, P2);
    a[3] = padd(E3, P3); a[7] = psub(E3, P3);
}

#define TWM  ((const C*)g_twm)
#define TWNT ((const C*)g_twnT)
#define TWS1 ((const C*)g_twS1)
#define TWS2 ((const C*)g_twS2)

// ---------------- stages (NT=256, 1 butterfly per thread per stage) --------------------

// fwd L=4096 (q=256): loads x DIRECTLY from gmem (logical t+256k, k<8; upper half of
// the zero-padded input is pruned), stores to swizzled smem. Twiddles from g_twS1.
__device__ __forceinline__ void fwd_stage1(C* __restrict__ z, const C* __restrict__ src, int t) {
    const int d0 = t & 15, d1 = (t >> 4) & 15;
    const int Cb = (d0 ^ d1) | (d1 << 4);
    C a[8], b[8];
#pragma unroll
    for (int k = 0; k < 8; k++) a[k] = src[t + (k << 8)];
    b[0] = a[0];
#pragma unroll
    for (int k = 1; k < 8; k++) b[k] = cmulK(a[k], w16c(k), -w16s(k));
    dft8f(a);   // X[2r]
    dft8f(b);   // X[2r+1]
    z[Cb] = a[0];
#define ST1(m) z[Cb ^ (((m) << 4) ^ ((m) << 8))] = cmul(((m) & 1) ? b[(m) >> 1] : a[(m) >> 1], TWS1[((m) - 1) * 256 + t])
    ST1(1); ST1(2); ST1(3); ST1(4); ST1(5); ST1(6); ST1(7); ST1(8);
    ST1(9); ST1(10); ST1(11); ST1(12); ST1(13); ST1(14); ST1(15);
#undef ST1
}

// fwd L=256 (q=16); twiddles from g_twS2
__device__ __forceinline__ void fwd_stage2(C* __restrict__ z, int t) {
    const int bb = t >> 4, j = t & 15;
    const int Cb = j | (bb << 4) | (bb << 8);
    C r[16];
#pragma unroll
    for (int k = 0; k < 16; k++) r[k] = z[Cb ^ (17 * k)];
    dft16<true>(r);
    z[Cb] = r[0];
#define ST2(m) z[Cb ^ (17 * (m))] = cmul(X16(r, m), TWS2[((m) - 1) * 16 + j])
    ST2(1); ST2(2); ST2(3); ST2(4); ST2(5); ST2(6); ST2(7); ST2(8);
    ST2(9); ST2(10); ST2(11); ST2(12); ST2(13); ST2(14); ST2(15);
#undef ST2
}

// fwd L=16 (q=1, no twiddles)
__device__ __forceinline__ void fwd_stage3(C* __restrict__ z, int t) {
    const int bl = t & 15, bh = t >> 4;
    const int Cb = bl | (((bl ^ bh) & 15) << 4) | (bh << 8);
    C r[16];
#pragma unroll
    for (int k = 0; k < 16; k++) r[k] = z[Cb ^ k];
    dft16<true>(r);
#pragma unroll
    for (int m = 0; m < 16; m++) z[Cb ^ m] = X16(r, m);
}

// inv L=16 (no twiddles)
__device__ __forceinline__ void inv_stage1(C* __restrict__ z, int t) {
    const int bl = t & 15, bh = t >> 4;
    const int Cb = bl | (((bl ^ bh) & 15) << 4) | (bh << 8);
    C r[16];
#pragma unroll
    for (int k = 0; k < 16; k++) r[k] = z[Cb ^ k];
    dft16<false>(r);
#pragma unroll
    for (int m = 0; m < 16; m++) z[Cb ^ m] = X16(r, m);
}

// inv L=256 (conj twiddles on inputs, from g_twS2)
__device__ __forceinline__ void inv_stage2(C* __restrict__ z, int t) {
    const int bb = t >> 4, j = t & 15;
    const int Cb = j | (bb << 4) | (bb << 8);
    C r[16];
    r[0] = z[Cb];
#define LD2(k) r[k] = cmulc(z[Cb ^ (17 * (k))], TWS2[((k) - 1) * 16 + j])
    LD2(1); LD2(2); LD2(3); LD2(4); LD2(5); LD2(6); LD2(7); LD2(8);
    LD2(9); LD2(10); LD2(11); LD2(12); LD2(13); LD2(14); LD2(15);
#undef LD2
    dft16<false>(r);
#pragma unroll
    for (int m = 0; m < 16; m++) z[Cb ^ (17 * m)] = X16(r, m);
}

// inv L=4096 (conj twiddles from g_twS1; only outputs k<8 kept): stores y to gmem, scaled.
__device__ __forceinline__ void inv_stage3(const C* __restrict__ z, C* __restrict__ dst, int t) {
    const int d0 = t & 15, d1 = (t >> 4) & 15;
    const int Cb = (d0 ^ d1) | (d1 << 4);
    C ae[8], ao[8];
    ae[0] = z[Cb];
#define LD3(k) { C v = cmulc(z[Cb ^ (((k) << 4) ^ ((k) << 8))], TWS1[((k) - 1) * 256 + t]); \
                 if ((k) & 1) ao[(k) >> 1] = v; else ae[(k) >> 1] = v; }
    LD3(1); LD3(2); LD3(3); LD3(4); LD3(5); LD3(6); LD3(7); LD3(8);
    LD3(9); LD3(10); LD3(11); LD3(12); LD3(13); LD3(14); LD3(15);
#undef LD3
    dft8i(ae);
    dft8i(ao);
#pragma unroll
    for (int k = 0; k < 8; k++) {
        C v = padd(ae[k], cmulK(ao[k], w16c(k), w16s(k)));
        dst[t + (k << 8)] = pmul(v, SCALEC);
    }
}

// ---------------- pointwise helpers ----------------------------------------------------

__device__ __forceinline__ void pw(C& Zk, C& Zm, C tw, C K1, C K2) {
    C cm = conjC(Zm);
    C E = pmul(HALFC, padd(Zk, cm));
    C D = psub(Zk, cm);
    C O = pmul(HALFC, mulmi(D));
    C OT = cmul(O, tw);
    C X1  = padd(E, OT);
    C X2c = psub(E, OT);
    C Y1  = cmul(X1, K1);
    C Y2c = cmulc(X2c, K2);
    C Ey = pmul(HALFC, padd(Y1, Y2c));
    C G  = pmul(HALFC, psub(Y1, Y2c));
    C Oy = cmulc(G, tw);
    Zk = padd(Ey, muli(Oy));
    Zm = padd(conjC(Ey), swapC(Oy));
}

__device__ __forceinline__ void unpackX(C Zk, C Zm, C tw, C& X1, C& X2) {
    C cm = conjC(Zm);
    C E = pmul(HALFC, padd(Zk, cm));
    C D = psub(Zk, cm);
    C O = pmul(HALFC, mulmi(D));
    C OT = cmul(O, tw);
    X1 = padd(E, OT);
    X2 = conjC(psub(E, OT));
}

// one pointwise iteration for unit index t
__device__ __forceinline__ void pw_iter(C* __restrict__ z, const ulonglong2* __restrict__ KAB, int t) {
    ulonglong2 Kv = KAB[t];
    C tw = TWNT[t];
    int c0, c1, c2; pair_digits(t, c0, c1, c2);
    int p = 256 * c0 + 16 * c1 + c2;
    int q = 4351 - p;
    int sp = PHI(p), sq = PHI(q);
    C Zk = z[sp], Zm = z[sq];
    pw(Zk, Zm, tw, Kv.x, Kv.y);
    z[sp] = Zk;
    z[sq] = Zm;
}

// ---------------- kernel spectra -------------------------------------------------------
__global__ __launch_bounds__(NT, 4) void kf_kernel(const float* __restrict__ kin) {
    __shared__ C z[M];
    const int h = blockIdx.x;
    const int tid = threadIdx.x;
    const C* krow2 = (const C*)(kin + (size_t)h * M);
    fwd_stage1(z, krow2, tid); __syncthreads();
    fwd_stage2(z, tid); __syncthreads();
    fwd_stage3(z, tid); __syncthreads();

    // boundary bins kk ≡ 0 (mod 16)
    if (tid < 128) {
        int u = tid;
        if (u == 0) {
            float zr, zi;
            unpackC(z[0], zr, zi);
            ulonglong2 v;
            v.x = packC(zr + zi, zr - zi);     // (Kf[0].re, Kf[M].re)
            v.y = conjC(z[8]);                 // Kf[M/2]
            g_KfCD[(size_t)h * 128] = v;
        } else {
            int p = 16 * (u & 15) + (u >> 4);
            int w = 256 - u;
            int q = 16 * (w & 15) + ((w >> 4) & 15);
            ulonglong2 v;
            unpackX(z[PHI(p)], z[PHI(q)], TWM[u << 3], v.x, v.y);  // Kf[16u], Kf[M-16u]
            g_KfCD[(size_t)h * 128 + u] = v;
        }
    }
    // main pairs
    for (int t = tid; t < NPAIR; t += NT) {
        int c0, c1, c2; pair_digits(t, c0, c1, c2);
        int p = 256 * c0 + 16 * c1 + c2;
        int q = 4351 - p;
        ulonglong2 v;
        unpackX(z[PHI(p)], z[PHI(q)], TWNT[t], v.x, v.y);          // Kf[kk], Kf[M-kk]
        g_KfAB[(size_t)h * NPAIR + t] = v;
    }
}

// ---------------- main conv (single row per CTA; same-h rows adjacent) ------------------
__global__ __launch_bounds__(NT, 4) void conv_kernel(const float* __restrict__ x,
                                                     float* __restrict__ y) {
    __shared__ C z[M];
    const int g = blockIdx.x;              // h-adjacent ordering for Kf L2 reuse
    const int h = g >> 2;
    const int b = g & 3;
    const int row = b * H + h;
    const int tid = threadIdx.x;
    const C* xrow2 = (const C*)(x + (size_t)row * M);
    C* yrow2 = (C*)(y + (size_t)row * M);

    fwd_stage1(z, xrow2, tid); __syncthreads();
    fwd_stage2(z, tid); __syncthreads();
    fwd_stage3(z, tid); __syncthreads();

    const ulonglong2* __restrict__ KAB = g_KfAB + (size_t)h * NPAIR;
    const ulonglong2* __restrict__ KCD = g_KfCD + (size_t)h * 128;
    // boundary bins kk ≡ 0 (mod 16)
    if (tid < 128) {
        int u = tid;
        if (u == 0) {
            ulonglong2 Kv = KCD[0];
            float zr, zi, kc, kd;
            unpackC(z[0], zr, zi);
            unpackC(Kv.x, kc, kd);
            float Y0 = (zr + zi) * kc;
            float Ym = (zr - zi) * kd;
            z[0] = packC(0.5f * (Y0 + Ym), 0.5f * (Y0 - Ym));
            z[8] = cmulc(z[8], Kv.y);                              // bin M/2
        } else {
            int p = 16 * (u & 15) + (u >> 4);
            int w = 256 - u;
            int q = 16 * (w & 15) + ((w >> 4) & 15);
            int sp = PHI(p), sq = PHI(q);
            ulonglong2 Kv = KCD[u];
            C Zk = z[sp], Zm = z[sq];
            pw(Zk, Zm, TWM[u << 3], Kv.x, Kv.y);
            z[sp] = Zk;
            z[sq] = Zm;
        }
    }
    // main pairs: 7 full unrolled iterations + masked 8th (NPAIR = 7.5 * NT)
#pragma unroll
    for (int i = 0; i < 7; i++) pw_iter(z, KAB, tid + i * NT);
    if (tid < NPAIR - 7 * NT) pw_iter(z, KAB, tid + 7 * NT);
    __syncthreads();
    inv_stage1(z, tid); __syncthreads();
    inv_stage2(z, tid); __syncthreads();
    inv_stage3(z, yrow2, tid);
}

extern "C" void kernel_launch(void* const* d_in, const int* in_sizes, int n_in,
                              void* d_out, int out_size) {
    const float* x;
    const float* k;
    if (in_sizes[0] == B * H * M) {           // x is the larger tensor
        x = (const float*)d_in[0];
        k = (const float*)d_in[1];
    } else {
        x = (const float*)d_in[1];
        k = (const float*)d_in[0];
    }
    float* y = (float*)d_out;

    const int ninit = M + NPAIR + 15 * 256 + 15 * 16;
    init_twiddles<<<(ninit + 511) / 512, 512>>>();
    kf_kernel<<<H, NT>>>(k);
    conv_kernel<<<B * H, NT>>>(x, y);
}

// round 16
// speedup vs baseline: 1.1790x; 1.0127x over previous
#include <cuda_runtime.h>

// FFT convolution (S4): y[b,0,h,:] = first 4096 samples of linear conv(x[b,h,:], k[0,h,:])
// via length-8192 real FFT implemented as 4096-pt complex FFT with even/odd packing.
//
// R15: pointwise operator algebraically folded into 3 precomputed constants per bin pair:
//   Zk' = P*Zk + Q*conj(Zm),  Zm' = -conj(Q*Zk) + S*Zm
// (P,Q,S computed once per h in kf_kernel). Conv pointwise drops from ~36 to ~22 instrs
// per pair and loses its twiddle dependency. Everything else = R14 (h-adjacent CTA
// scheduling, gmem-direct first/last stages, stage-twiddle tables, packed f32x2, occ 4).

#define M 4096
#define H 1024
#define B 4
#define NT 256
#define NPAIR 1920           // pairs with kk !≡ 0 (mod 16), kk < 2048

#define PHI(a) ((a) ^ (((a) >> 4) & 15) ^ ((((a) >> 8) & 15) << 4))

typedef unsigned long long C;

__device__ float2 g_twm[M];              // e^{-2pi i e / M}
__device__ float2 g_twnT[NPAIR];         // e^{-pi i kk(t) / M}, t-ordered (kf only)
__device__ float2 g_twS1[15 * 256];      // [(m-1)*256 + t] = e^{-2pi i m t / 4096}
__device__ float2 g_twS2[15 * 16];       // [(m-1)*16 + j]   = e^{-2pi i m j / 256}
__device__ ulonglong2 g_KfPQ[H * NPAIR]; // {P, Q} per pair
__device__ C g_KfS[H * NPAIR];           // S per pair
__device__ ulonglong2 g_KfPQb[H * 128];  // boundary: u=0 -> {(Kf0.re,KfM.re), Kf[M/2]}; u>0 -> {P,Q}
__device__ C g_KfSb[H * 128];            // boundary S (u>0)

// ---------------- packed complex: lo 32 bits = re, hi 32 bits = im ---------------------
__device__ __forceinline__ C packC(float re, float im) {
    C r; asm("mov.b64 %0, {%1, %2};" : "=l"(r) : "f"(re), "f"(im)); return r;
}
__device__ __forceinline__ void unpackC(C a, float& re, float& im) {
    asm("mov.b64 {%0, %1}, %2;" : "=f"(re), "=f"(im) : "l"(a));
}
__device__ __forceinline__ C padd(C a, C b) {
    C r; asm("add.rn.f32x2 %0, %1, %2;" : "=l"(r) : "l"(a), "l"(b)); return r;
}
__device__ __forceinline__ C pmul(C a, C b) {
    C r; asm("mul.rn.f32x2 %0, %1, %2;" : "=l"(r) : "l"(a), "l"(b)); return r;
}
__device__ __forceinline__ C pfma(C a, C b, C c) {
    C r; asm("fma.rn.f32x2 %0, %1, %2, %3;" : "=l"(r) : "l"(a), "l"(b), "l"(c)); return r;
}
__device__ __forceinline__ C psub(C a, C b) {           // a - b = fma(b, -1, a)
    return pfma(b, 0xBF800000BF800000ULL, a);
}
__device__ __forceinline__ C swapC(C a) {               // (im, re)
    unsigned lo, hi; asm("mov.b64 {%0, %1}, %2;" : "=r"(lo), "=r"(hi) : "l"(a));
    C r; asm("mov.b64 %0, {%1, %2};" : "=l"(r) : "r"(hi), "r"(lo)); return r;
}
__device__ __forceinline__ C conjC(C a)  { return a ^ 0x8000000000000000ULL; }
__device__ __forceinline__ C negconjC(C a) { return a ^ 0x0000000080000000ULL; }  // -conj(a)
__device__ __forceinline__ C muli(C a)   { return swapC(a) ^ 0x80000000ULL; }
__device__ __forceinline__ C mulmi(C a)  { return swapC(a) ^ 0x8000000000000000ULL; }
__device__ __forceinline__ C splat_re(C a) {
    unsigned lo, hi; asm("mov.b64 {%0, %1}, %2;" : "=r"(lo), "=r"(hi) : "l"(a));
    C r; asm("mov.b64 %0, {%1, %2};" : "=l"(r) : "r"(lo), "r"(lo)); return r;
}
__device__ __forceinline__ C splat_im(C a) {
    unsigned lo, hi; asm("mov.b64 {%0, %1}, %2;" : "=r"(lo), "=r"(hi) : "l"(a));
    C r; asm("mov.b64 %0, {%1, %2};" : "=l"(r) : "r"(hi), "r"(hi)); return r;
}
__device__ __forceinline__ C cmul(C a, C b) {
    return pfma(splat_im(a), muli(b), pmul(splat_re(a), b));
}
__device__ __forceinline__ C cmul_acc(C a, C b, C acc) {   // a*b + acc
    return pfma(splat_im(a), muli(b), pfma(splat_re(a), b, acc));
}
__device__ __forceinline__ C cmulc(C a, C b) { return cmul(a, conjC(b)); }
__device__ __forceinline__ C cmulK(C a, float cr, float ci) {
    return pfma(splat_im(a), packC(-ci, cr), pmul(splat_re(a), packC(cr, ci)));
}

#define CC 0.70710678118654752f
#define HALFC 0x3F0000003F000000ULL     // (0.5, 0.5)
#define SCALEC 0x3980000039800000ULL    // (2^-12, 2^-12) = 1/M

// cos/sin(k*pi/8)
__device__ __forceinline__ constexpr float w16c(int k) {
    return (k == 0) ? 1.f : (k == 1) ? 0.9238795325112867f : (k == 2) ? 0.7071067811865476f
         : (k == 3) ? 0.3826834323650898f : (k == 4) ? 0.f : (k == 5) ? -0.3826834323650898f
         : (k == 6) ? -0.7071067811865476f : (k == 7) ? -0.9238795325112867f
         : (k == 8) ? -1.f : -0.9238795325112867f;
}
__device__ __forceinline__ constexpr float w16s(int k) {
    return (k == 0) ? 0.f : (k == 1) ? 0.3826834323650898f : (k == 2) ? 0.7071067811865476f
         : (k == 3) ? 0.9238795325112867f : (k == 4) ? 1.f : (k == 5) ? 0.9238795325112867f
         : (k == 6) ? 0.7071067811865476f : (k == 7) ? 0.3826834323650898f
         : (k == 8) ? 0.f : -0.3826834323650898f;
}

// pair enumeration (c1 fastest for conflict-free smem)
__device__ __forceinline__ void pair_digits(int t, int& c0, int& c1, int& c2) {
    c0 = 1 + (t >> 7);
    c1 = t & 15;
    c2 = (t >> 4) & 7;
}

__global__ void init_twiddles() {
    int i = blockIdx.x * blockDim.x + threadIdx.x;
    if (i < M) {
        float s, c;
        sincospif(-2.0f * (float)i / (float)M, &s, &c);
        g_twm[i] = make_float2(c, s);
    }
    int t = i - M;
    if (t >= 0 && t < NPAIR) {
        int c0, c1, c2; pair_digits(t, c0, c1, c2);
        int kk = 256 * c2 + 16 * c1 + c0;
        float s, c;
        sincospif(-(float)kk / (float)M, &s, &c);
        g_twnT[t] = make_float2(c, s);
    }
    int i2 = i - M - NPAIR;
    if (i2 >= 0 && i2 < 15 * 256) {
        int m = (i2 >> 8) + 1, tt = i2 & 255;
        float s, c;
        sincospif(-2.0f * (float)(m * tt) / 4096.0f, &s, &c);
        g_twS1[i2] = make_float2(c, s);
    }
    int i3 = i - M - NPAIR - 15 * 256;
    if (i3 >= 0 && i3 < 15 * 16) {
        int m = (i3 >> 4) + 1, j = i3 & 15;
        float s, c;
        sincospif(-2.0f * (float)(m * j) / 256.0f, &s, &c);
        g_twS2[i3] = make_float2(c, s);
    }
}

// ---------------- DFT building blocks --------------------------------------------------

template <bool FWD>
__device__ __forceinline__ void dft4(C& A, C& Bv, C& Cv, C& D) {
    C t0 = padd(A, Cv), t1 = psub(A, Cv), t2 = padd(Bv, D), t3 = psub(Bv, D);
    A = padd(t0, t2); Cv = psub(t0, t2);
    C j = FWD ? mulmi(t3) : muli(t3);
    Bv = padd(t1, j); D = psub(t1, j);
}

template <bool FWD, int E>
__device__ __forceinline__ C cw16(C a) {
    if (E == 4) return FWD ? mulmi(a) : muli(a);
    return cmulK(a, w16c(E), FWD ? -w16s(E) : w16s(E));
}

// natural input, output X[m] at slot perm(m) = ((m&3)<<2)|(m>>2)
template <bool FWD>
__device__ __forceinline__ void dft16(C* r) {
    dft4<FWD>(r[0], r[4], r[8], r[12]);
    dft4<FWD>(r[1], r[5], r[9], r[13]);
    dft4<FWD>(r[2], r[6], r[10], r[14]);
    dft4<FWD>(r[3], r[7], r[11], r[15]);
    r[5]  = cw16<FWD, 1>(r[5]);
    r[9]  = cw16<FWD, 2>(r[9]);
    r[13] = cw16<FWD, 3>(r[13]);
    r[6]  = cw16<FWD, 2>(r[6]);
    r[10] = cw16<FWD, 4>(r[10]);
    r[14] = cw16<FWD, 6>(r[14]);
    r[7]  = cw16<FWD, 3>(r[7]);
    r[11] = cw16<FWD, 6>(r[11]);
    r[15] = cw16<FWD, 9>(r[15]);
    dft4<FWD>(r[0],  r[1],  r[2],  r[3]);
    dft4<FWD>(r[4],  r[5],  r[6],  r[7]);
    dft4<FWD>(r[8],  r[9],  r[10], r[11]);
    dft4<FWD>(r[12], r[13], r[14], r[15]);
}
#define X16(r, m) (r)[(((m) & 3) << 2) | ((m) >> 2)]

__device__ __forceinline__ void dft8f(C* a) {
    C s0 = padd(a[0], a[4]), s1 = psub(a[0], a[4]), s2 = padd(a[2], a[6]), s3 = psub(a[2], a[6]);
    C E0 = padd(s0, s2), E2 = psub(s0, s2);
    C js = mulmi(s3);
    C E1 = padd(s1, js), E3 = psub(s1, js);
    C t0 = padd(a[1], a[5]), t1 = psub(a[1], a[5]), t2 = padd(a[3], a[7]), t3 = psub(a[3], a[7]);
    C O0 = padd(t0, t2), O2 = psub(t0, t2);
    C jt = mulmi(t3);
    C O1 = padd(t1, jt), O3 = psub(t1, jt);
    const C CC2 = packC(CC, CC);
    C P1 = pmul(CC2, padd(mulmi(O1), O1));
    C P2 = mulmi(O2);
    C P3 = pmul(CC2, psub(mulmi(O3), O3));
    a[0] = padd(E0, O0); a[4] = psub(E0, O0);
    a[1] = padd(E1, P1); a[5] = psub(E1, P1);
    a[2] = padd(E2, P2); a[6] = psub(E2, P2);
    a[3] = padd(E3, P3); a[7] = psub(E3, P3);
}

__device__ __forceinline__ void dft8i(C* a) {
    C s0 = padd(a[0], a[4]), s1 = psub(a[0], a[4]), s2 = padd(a[2], a[6]), s3 = psub(a[2], a[6]);
    C E0 = padd(s0, s2), E2 = psub(s0, s2);
    C js = muli(s3);
    C E1 = padd(s1, js), E3 = psub(s1, js);
    C t0 = padd(a[1], a[5]), t1 = psub(a[1], a[5]), t2 = padd(a[3], a[7]), t3 = psub(a[3], a[7]);
    C O0 = padd(t0, t2), O2 = psub(t0, t2);
    C jt = muli(t3);
    C O1 = padd(t1, jt), O3 = psub(t1, jt);
    const C CC2 = packC(CC, CC);
    C P1 = pmul(CC2, padd(muli(O1), O1));
    C P2 = muli(O2);
    C P3 = pmul(CC2, psub(muli(O3), O3));
    a[0] = padd(E0, O0); a[4] = psub(E0, O0);
    a[1] = padd(E1, P1); a[5] = psub(E1, P1);
    a[2] = padd(E2, P2); a[6] = psub(E2, P2);
    a[3] = padd(E3, P3); a[7] = psub(E3, P3);
}

#define TWM  ((const C*)g_twm)
#define TWNT ((const C*)g_twnT)
#define TWS1 ((const C*)g_twS1)
#define TWS2 ((const C*)g_twS2)

// ---------------- stages (NT=256, 1 butterfly per thread per stage) --------------------

// fwd L=4096 (q=256): loads x DIRECTLY from gmem (logical t+256k, k<8; upper half of
// the zero-padded input is pruned), stores to swizzled smem. Twiddles from g_twS1.
__device__ __forceinline__ void fwd_stage1(C* __restrict__ z, const C* __restrict__ src, int t) {
    const int d0 = t & 15, d1 = (t >> 4) & 15;
    const int Cb = (d0 ^ d1) | (d1 << 4);
    C a[8], b[8];
#pragma unroll
    for (int k = 0; k < 8; k++) a[k] = src[t + (k << 8)];
    b[0] = a[0];
#pragma unroll
    for (int k = 1; k < 8; k++) b[k] = cmulK(a[k], w16c(k), -w16s(k));
    dft8f(a);   // X[2r]
    dft8f(b);   // X[2r+1]
    z[Cb] = a[0];
#define ST1(m) z[Cb ^ (((m) << 4) ^ ((m) << 8))] = cmul(((m) & 1) ? b[(m) >> 1] : a[(m) >> 1], TWS1[((m) - 1) * 256 + t])
    ST1(1); ST1(2); ST1(3); ST1(4); ST1(5); ST1(6); ST1(7); ST1(8);
    ST1(9); ST1(10); ST1(11); ST1(12); ST1(13); ST1(14); ST1(15);
#undef ST1
}

// fwd L=256 (q=16); twiddles from g_twS2
__device__ __forceinline__ void fwd_stage2(C* __restrict__ z, int t) {
    const int bb = t >> 4, j = t & 15;
    const int Cb = j | (bb << 4) | (bb << 8);
    C r[16];
#pragma unroll
    for (int k = 0; k < 16; k++) r[k] = z[Cb ^ (17 * k)];
    dft16<true>(r);
    z[Cb] = r[0];
#define ST2(m) z[Cb ^ (17 * (m))] = cmul(X16(r, m), TWS2[((m) - 1) * 16 + j])
    ST2(1); ST2(2); ST2(3); ST2(4); ST2(5); ST2(6); ST2(7); ST2(8);
    ST2(9); ST2(10); ST2(11); ST2(12); ST2(13); ST2(14); ST2(15);
#undef ST2
}

// fwd L=16 (q=1, no twiddles)
__device__ __forceinline__ void fwd_stage3(C* __restrict__ z, int t) {
    const int bl = t & 15, bh = t >> 4;
    const int Cb = bl | (((bl ^ bh) & 15) << 4) | (bh << 8);
    C r[16];
#pragma unroll
    for (int k = 0; k < 16; k++) r[k] = z[Cb ^ k];
    dft16<true>(r);
#pragma unroll
    for (int m = 0; m < 16; m++) z[Cb ^ m] = X16(r, m);
}

// inv L=16 (no twiddles)
__device__ __forceinline__ void inv_stage1(C* __restrict__ z, int t) {
    const int bl = t & 15, bh = t >> 4;
    const int Cb = bl | (((bl ^ bh) & 15) << 4) | (bh << 8);
    C r[16];
#pragma unroll
    for (int k = 0; k < 16; k++) r[k] = z[Cb ^ k];
    dft16<false>(r);
#pragma unroll
    for (int m = 0; m < 16; m++) z[Cb ^ m] = X16(r, m);
}

// inv L=256 (conj twiddles on inputs, from g_twS2)
__device__ __forceinline__ void inv_stage2(C* __restrict__ z, int t) {
    const int bb = t >> 4, j = t & 15;
    const int Cb = j | (bb << 4) | (bb << 8);
    C r[16];
    r[0] = z[Cb];
#define LD2(k) r[k] = cmulc(z[Cb ^ (17 * (k))], TWS2[((k) - 1) * 16 + j])
    LD2(1); LD2(2); LD2(3); LD2(4); LD2(5); LD2(6); LD2(7); LD2(8);
    LD2(9); LD2(10); LD2(11); LD2(12); LD2(13); LD2(14); LD2(15);
#undef LD2
    dft16<false>(r);
#pragma unroll
    for (int m = 0; m < 16; m++) z[Cb ^ (17 * m)] = X16(r, m);
}

// inv L=4096 (conj twiddles from g_twS1; only outputs k<8 kept): stores y to gmem, scaled.
__device__ __forceinline__ void inv_stage3(const C* __restrict__ z, C* __restrict__ dst, int t) {
    const int d0 = t & 15, d1 = (t >> 4) & 15;
    const int Cb = (d0 ^ d1) | (d1 << 4);
    C ae[8], ao[8];
    ae[0] = z[Cb];
#define LD3(k) { C v = cmulc(z[Cb ^ (((k) << 4) ^ ((k) << 8))], TWS1[((k) - 1) * 256 + t]); \
                 if ((k) & 1) ao[(k) >> 1] = v; else ae[(k) >> 1] = v; }
    LD3(1); LD3(2); LD3(3); LD3(4); LD3(5); LD3(6); LD3(7); LD3(8);
    LD3(9); LD3(10); LD3(11); LD3(12); LD3(13); LD3(14); LD3(15);
#undef LD3
    dft8i(ae);
    dft8i(ao);
#pragma unroll
    for (int k = 0; k < 8; k++) {
        C v = padd(ae[k], cmulK(ao[k], w16c(k), w16s(k)));
        dst[t + (k << 8)] = pmul(v, SCALEC);
    }
}

// ---------------- pointwise ------------------------------------------------------------

// folded operator: Zk' = P*Zk + Q*conj(Zm);  Zm' = -conj(Q*Zk) + S*Zm
__device__ __forceinline__ void pw2(C& Zk, C& Zm, C P, C Q, C S) {
    C zk0 = Zk;
    C cm = conjC(Zm);
    C nk = cmul_acc(Q, cm, cmul(P, zk0));
    C qz = cmul(Q, zk0);
    C nm = cmul_acc(S, Zm, negconjC(qz));
    Zk = nk;
    Zm = nm;
}

// fold (X1=Kf[kk], X2=Kf[M-kk], tw) -> (P, Q, S)
__device__ __forceinline__ void makePQS(C X1, C X2, C tw, C& P, C& Q, C& S) {
    float cc_, ss_;
    unpackC(tw, cc_, ss_);
    float al = 0.5f * (1.f + ss_), be = 0.5f * (1.f - ss_), ga = 0.5f * cc_;
    C K2c = conjC(X2);
    C AL = packC(al, al), BE = packC(be, be), GA = packC(ga, ga);
    P = pfma(BE, K2c, pmul(AL, X1));
    Q = muli(pmul(GA, psub(X1, K2c)));
    S = conjC(pfma(AL, K2c, pmul(BE, X1)));
}

// Hermitian unpack (kf): X1 = X[kk], X2 = X[4096-kk]
__device__ __forceinline__ void unpackX(C Zk, C Zm, C tw, C& X1, C& X2) {
    C cm = conjC(Zm);
    C E = pmul(HALFC, padd(Zk, cm));
    C D = psub(Zk, cm);
    C O = pmul(HALFC, mulmi(D));
    C OT = cmul(O, tw);
    X1 = padd(E, OT);
    X2 = conjC(psub(E, OT));
}

// one conv pointwise iteration for unit index t
__device__ __forceinline__ void pw_iter(C* __restrict__ z, const ulonglong2* __restrict__ KPQ,
                                        const C* __restrict__ KS, int t) {
    ulonglong2 Kv = KPQ[t];
    C Sv = KS[t];
    int c0, c1, c2; pair_digits(t, c0, c1, c2);
    int p = 256 * c0 + 16 * c1 + c2;
    int q = 4351 - p;
    int sp = PHI(p), sq = PHI(q);
    C Zk = z[sp], Zm = z[sq];
    pw2(Zk, Zm, Kv.x, Kv.y, Sv);
    z[sp] = Zk;
    z[sq] = Zm;
}

// ---------------- kernel spectra -------------------------------------------------------
__global__ __launch_bounds__(NT, 4) void kf_kernel(const float* __restrict__ kin) {
    __shared__ C z[M];
    const int h = blockIdx.x;
    const int tid = threadIdx.x;
    const C* krow2 = (const C*)(kin + (size_t)h * M);
    fwd_stage1(z, krow2, tid); __syncthreads();
    fwd_stage2(z, tid); __syncthreads();
    fwd_stage3(z, tid); __syncthreads();

    // boundary bins kk ≡ 0 (mod 16)
    if (tid < 128) {
        int u = tid;
        if (u == 0) {
            float zr, zi;
            unpackC(z[0], zr, zi);
            ulonglong2 v;
            v.x = packC(zr + zi, zr - zi);     // (Kf[0].re, Kf[M].re)
            v.y = conjC(z[8]);                 // Kf[M/2]
            g_KfPQb[(size_t)h * 128] = v;
        } else {
            int p = 16 * (u & 15) + (u >> 4);
            int w = 256 - u;
            int q = 16 * (w & 15) + ((w >> 4) & 15);
            C X1, X2, tw = TWM[u << 3];
            unpackX(z[PHI(p)], z[PHI(q)], tw, X1, X2);  // Kf[16u], Kf[M-16u]
            ulonglong2 v; C Sv;
            makePQS(X1, X2, tw, v.x, v.y, Sv);
            g_KfPQb[(size_t)h * 128 + u] = v;
            g_KfSb[(size_t)h * 128 + u] = Sv;
        }
    }
    // main pairs
    for (int t = tid; t < NPAIR; t += NT) {
        int c0, c1, c2; pair_digits(t, c0, c1, c2);
        int p = 256 * c0 + 16 * c1 + c2;
        int q = 4351 - p;
        C X1, X2, tw = TWNT[t];
        unpackX(z[PHI(p)], z[PHI(q)], tw, X1, X2);      // Kf[kk], Kf[M-kk]
        ulonglong2 v; C Sv;
        makePQS(X1, X2, tw, v.x, v.y, Sv);
        g_KfPQ[(size_t)h * NPAIR + t] = v;
        g_KfS[(size_t)h * NPAIR + t] = Sv;
    }
}

// ---------------- main conv (single row per CTA; same-h rows adjacent) ------------------
__global__ __launch_bounds__(NT, 4) void conv_kernel(const float* __restrict__ x,
                                                     float* __restrict__ y) {
    __shared__ C z[M];
    const int g = blockIdx.x;              // h-adjacent ordering for Kf L2 reuse
    const int h = g >> 2;
    const int b = g & 3;
    const int row = b * H + h;
    const int tid = threadIdx.x;
    const C* xrow2 = (const C*)(x + (size_t)row * M);
    C* yrow2 = (C*)(y + (size_t)row * M);

    fwd_stage1(z, xrow2, tid); __syncthreads();
    fwd_stage2(z, tid); __syncthreads();
    fwd_stage3(z, tid); __syncthreads();

    const ulonglong2* __restrict__ KPQ = g_KfPQ + (size_t)h * NPAIR;
    const C* __restrict__ KS = g_KfS + (size_t)h * NPAIR;
    const ulonglong2* __restrict__ KPQb = g_KfPQb + (size_t)h * 128;
    const C* __restrict__ KSb = g_KfSb + (size_t)h * 128;
    // boundary bins kk ≡ 0 (mod 16)
    if (tid < 128) {
        int u = tid;
        if (u == 0) {
            ulonglong2 Kv = KPQb[0];
            float zr, zi, kc, kd;
            unpackC(z[0], zr, zi);
            unpackC(Kv.x, kc, kd);
            float Y0 = (zr + zi) * kc;
            float Ym = (zr - zi) * kd;
            z[0] = packC(0.5f * (Y0 + Ym), 0.5f * (Y0 - Ym));
            z[8] = cmulc(z[8], Kv.y);                              // bin M/2
        } else {
            int p = 16 * (u & 15) + (u >> 4);
            int w = 256 - u;
            int q = 16 * (w & 15) + ((w >> 4) & 15);
            int sp = PHI(p), sq = PHI(q);
            ulonglong2 Kv = KPQb[u];
            C Sv = KSb[u];
            C Zk = z[sp], Zm = z[sq];
            pw2(Zk, Zm, Kv.x, Kv.y, Sv);
            z[sp] = Zk;
            z[sq] = Zm;
        }
    }
    // main pairs: 7 full unrolled iterations + masked 8th (NPAIR = 7.5 * NT)
#pragma unroll
    for (int i = 0; i < 7; i++) pw_iter(z, KPQ, KS, tid + i * NT);
    if (tid < NPAIR - 7 * NT) pw_iter(z, KPQ, KS, tid + 7 * NT);
    __syncthreads();
    inv_stage1(z, tid); __syncthreads();
    inv_stage2(z, tid); __syncthreads();
    inv_stage3(z, yrow2, tid);
}

extern "C" void kernel_launch(void* const* d_in, const int* in_sizes, int n_in,
                              void* d_out, int out_size) {
    const float* x;
    const float* k;
    if (in_sizes[0] == B * H * M) {           // x is the larger tensor
        x = (const float*)d_in[0];
        k = (const float*)d_in[1];
    } else {
        x = (const float*)d_in[1];
        k = (const float*)d_in[0];
    }
    float* y = (float*)d_out;

    const int ninit = M + NPAIR + 15 * 256 + 15 * 16;
    init_twiddles<<<(ninit + 511) / 512, 512>>>();
    kf_kernel<<<H, NT>>>(k);
    conv_kernel<<<B * H, NT>>>(x, y);
}